// round 1
// baseline (speedup 1.0000x reference)
#include <cuda_runtime.h>
#include <math.h>

// Problem constants
// B=8, T=2048, P=16, S=8, A=16, D=768, H=768, 3H=2304, 4D=3072

// ---------------- scratch (device globals; no dynamic allocation) ----------------
__device__ float g_ps[8 * 16];
__device__ float g_h[8 * 768];
__device__ float g_R1[16384 * 768];        // relu(video@mv_w1+b1)
__device__ float g_segmean[128 * 768];     // per (b,p) segment mean of g_R1
__device__ float g_vp_pre[8 * 768];
__device__ float g_vp[8 * 768];
__device__ float g_para_h[128 * 768];
__device__ float g_para_o[128 * 768];
__device__ float g_pr[8 * 768];
__device__ float g_qh[8 * 768];
__device__ float g_q[8 * 768];
__device__ float g_th[1024 * 768];         // shared hidden temp for a_t / a_b
__device__ float g_at[1024 * 768];
__device__ float g_ab[1024 * 768];
__device__ float g_inp[1024 * 3072];
__device__ float g_preh[1024 * 3072];
__device__ float g_x[1024 * 768];
__device__ float g_gi[1024 * 2304];
__device__ float g_gh[8 * 2304];
__device__ float g_states[128 * 768];
__device__ float g_hid[128 * 768];

// ---------------- softmax over paras_score + init h = state0 ----------------
__global__ void k_softmax_init(const float* __restrict__ scores,
                               const float* __restrict__ state0) {
    int tid = threadIdx.x;
    int warp = tid >> 5, lane = tid & 31;
    if (warp < 8) {
        float v = (lane < 16) ? scores[warp * 16 + lane] : -1e30f;
        float m = v;
        #pragma unroll
        for (int o = 16; o > 0; o >>= 1) m = fmaxf(m, __shfl_xor_sync(0xffffffffu, m, o));
        float e = (lane < 16) ? expf(v - m) : 0.f;
        float s = e;
        #pragma unroll
        for (int o = 16; o > 0; o >>= 1) s += __shfl_xor_sync(0xffffffffu, s, o);
        if (lane < 16) g_ps[warp * 16 + lane] = e / s;
    }
    for (int i = tid; i < 8 * 768; i += blockDim.x) g_h[i] = state0[i % 768];
}

// ---------------- big GEMM: C = [relu](A[M,K] @ W + bias), W is [K,N] or [N,K] (TRANSB)
// 128x128 block tile, BK=8, 256 threads, 8x8 micro-tile per thread
template <bool RELU, bool TRANSB>
__global__ void __launch_bounds__(256, 2) k_gemm128(
    const float* __restrict__ A, const float* __restrict__ W,
    const float* __restrict__ bias, float* __restrict__ C,
    int M, int N, int K) {
    __shared__ __align__(16) float As[8][128];
    __shared__ __align__(16) float Ws[8][128];
    const int tid = threadIdx.x;
    const int row0 = blockIdx.y * 128;
    const int col0 = blockIdx.x * 128;
    const int ty = tid >> 4, tx = tid & 15;
    const int arow = tid >> 1;
    const int acol = (tid & 1) * 4;

    float acc[8][8];
    #pragma unroll
    for (int i = 0; i < 8; i++)
        #pragma unroll
        for (int j = 0; j < 8; j++) acc[i][j] = 0.f;

    for (int k0 = 0; k0 < K; k0 += 8) {
        float4 av = make_float4(0.f, 0.f, 0.f, 0.f);
        int gr = row0 + arow;
        if (gr < M) av = *reinterpret_cast<const float4*>(A + (size_t)gr * K + k0 + acol);
        As[acol + 0][arow] = av.x;
        As[acol + 1][arow] = av.y;
        As[acol + 2][arow] = av.z;
        As[acol + 3][arow] = av.w;
        if (!TRANSB) {
            int wrow = tid >> 5;
            int wcol = (tid & 31) * 4;
            float4 wv = *reinterpret_cast<const float4*>(W + (size_t)(k0 + wrow) * N + col0 + wcol);
            *reinterpret_cast<float4*>(&Ws[wrow][wcol]) = wv;
        } else {
            int wn = tid >> 1;
            int wk = (tid & 1) * 4;
            float4 wv = *reinterpret_cast<const float4*>(W + (size_t)(col0 + wn) * K + k0 + wk);
            Ws[wk + 0][wn] = wv.x;
            Ws[wk + 1][wn] = wv.y;
            Ws[wk + 2][wn] = wv.z;
            Ws[wk + 3][wn] = wv.w;
        }
        __syncthreads();
        #pragma unroll
        for (int k = 0; k < 8; k++) {
            float4 a0 = *reinterpret_cast<const float4*>(&As[k][ty * 4]);
            float4 a1 = *reinterpret_cast<const float4*>(&As[k][64 + ty * 4]);
            float4 b0 = *reinterpret_cast<const float4*>(&Ws[k][tx * 4]);
            float4 b1 = *reinterpret_cast<const float4*>(&Ws[k][64 + tx * 4]);
            float ar[8] = {a0.x, a0.y, a0.z, a0.w, a1.x, a1.y, a1.z, a1.w};
            float br[8] = {b0.x, b0.y, b0.z, b0.w, b1.x, b1.y, b1.z, b1.w};
            #pragma unroll
            for (int i = 0; i < 8; i++)
                #pragma unroll
                for (int j = 0; j < 8; j++)
                    acc[i][j] = fmaf(ar[i], br[j], acc[i][j]);
        }
        __syncthreads();
    }

    float4 bv0 = *reinterpret_cast<const float4*>(bias + col0 + tx * 4);
    float4 bv1 = *reinterpret_cast<const float4*>(bias + col0 + 64 + tx * 4);
    float bb[8] = {bv0.x, bv0.y, bv0.z, bv0.w, bv1.x, bv1.y, bv1.z, bv1.w};
    #pragma unroll
    for (int i = 0; i < 8; i++) {
        int r = row0 + ((i < 4) ? (ty * 4 + i) : (64 + ty * 4 + i - 4));
        if (r >= M) continue;
        float o[8];
        #pragma unroll
        for (int j = 0; j < 8; j++) {
            float v = acc[i][j] + bb[j];
            if (RELU) v = fmaxf(v, 0.f);
            o[j] = v;
        }
        *reinterpret_cast<float4*>(C + (size_t)r * N + col0 + tx * 4) =
            make_float4(o[0], o[1], o[2], o[3]);
        *reinterpret_cast<float4*>(C + (size_t)r * N + col0 + 64 + tx * 4) =
            make_float4(o[4], o[5], o[6], o[7]);
    }
}

// ---------------- small-M GEMM: 16x128 block tile, BK=32, 256 threads ----------------
template <bool RELU>
__global__ void __launch_bounds__(256) k_gemm16(
    const float* __restrict__ A, const float* __restrict__ W,
    const float* __restrict__ bias, float* __restrict__ C,
    int M, int N, int K) {
    __shared__ __align__(16) float As[32][16];
    __shared__ __align__(16) float Ws[32][128];
    const int tid = threadIdx.x;
    const int row0 = blockIdx.y * 16;
    const int col0 = blockIdx.x * 128;
    const int row = tid >> 4;  // 0..15
    const int cg = tid & 15;

    float acc[8];
    #pragma unroll
    for (int j = 0; j < 8; j++) acc[j] = 0.f;

    for (int k0 = 0; k0 < K; k0 += 32) {
        if (tid < 128) {
            int ar = tid >> 3, ac = (tid & 7) * 4;
            float4 av = make_float4(0.f, 0.f, 0.f, 0.f);
            int gr = row0 + ar;
            if (gr < M) av = *reinterpret_cast<const float4*>(A + (size_t)gr * K + k0 + ac);
            As[ac + 0][ar] = av.x;
            As[ac + 1][ar] = av.y;
            As[ac + 2][ar] = av.z;
            As[ac + 3][ar] = av.w;
        }
        #pragma unroll
        for (int j = 0; j < 4; j++) {
            int wr = (tid >> 5) + j * 8;
            int wc = (tid & 31) * 4;
            float4 wv = *reinterpret_cast<const float4*>(W + (size_t)(k0 + wr) * N + col0 + wc);
            *reinterpret_cast<float4*>(&Ws[wr][wc]) = wv;
        }
        __syncthreads();
        #pragma unroll
        for (int k = 0; k < 32; k++) {
            float a = As[k][row];
            float4 b0 = *reinterpret_cast<const float4*>(&Ws[k][cg * 4]);
            float4 b1 = *reinterpret_cast<const float4*>(&Ws[k][64 + cg * 4]);
            acc[0] = fmaf(a, b0.x, acc[0]);
            acc[1] = fmaf(a, b0.y, acc[1]);
            acc[2] = fmaf(a, b0.z, acc[2]);
            acc[3] = fmaf(a, b0.w, acc[3]);
            acc[4] = fmaf(a, b1.x, acc[4]);
            acc[5] = fmaf(a, b1.y, acc[5]);
            acc[6] = fmaf(a, b1.z, acc[6]);
            acc[7] = fmaf(a, b1.w, acc[7]);
        }
        __syncthreads();
    }

    int r = row0 + row;
    if (r < M) {
        float4 bv0 = *reinterpret_cast<const float4*>(bias + col0 + cg * 4);
        float4 bv1 = *reinterpret_cast<const float4*>(bias + col0 + 64 + cg * 4);
        float o[8];
        o[0] = acc[0] + bv0.x; o[1] = acc[1] + bv0.y;
        o[2] = acc[2] + bv0.z; o[3] = acc[3] + bv0.w;
        o[4] = acc[4] + bv1.x; o[5] = acc[5] + bv1.y;
        o[6] = acc[6] + bv1.z; o[7] = acc[7] + bv1.w;
        if (RELU) {
            #pragma unroll
            for (int j = 0; j < 8; j++) o[j] = fmaxf(o[j], 0.f);
        }
        *reinterpret_cast<float4*>(C + (size_t)r * N + col0 + cg * 4) =
            make_float4(o[0], o[1], o[2], o[3]);
        *reinterpret_cast<float4*>(C + (size_t)r * N + col0 + 64 + cg * 4) =
            make_float4(o[4], o[5], o[6], o[7]);
    }
}

// ---------------- per-(b,p) segment mean of g_R1 over 128 timesteps ----------------
__global__ void k_segmean() {
    int bp = blockIdx.y;                       // 0..127 (b*16+p)
    int d = blockIdx.x * 256 + threadIdx.x;    // 0..767
    const float* src = g_R1 + (size_t)bp * 128 * 768 + d;
    float acc = 0.f;
    #pragma unroll 8
    for (int j = 0; j < 128; j++) acc += src[(size_t)j * 768];
    g_segmean[bp * 768 + d] = acc * (1.f / 128.f);
}

// ---------------- out[b,:] = sum_p ps[b,p] * in[b*16+p,:] ----------------
__global__ void k_wsum(const float* __restrict__ in, float* __restrict__ out) {
    int b = blockIdx.y;
    int d = blockIdx.x * 256 + threadIdx.x;
    float acc = 0.f;
    #pragma unroll
    for (int p = 0; p < 16; p++)
        acc = fmaf(g_ps[b * 16 + p], in[(size_t)(b * 16 + p) * 768 + d], acc);
    out[b * 768 + d] = acc;
}

// ---------------- build mlp_pre input: [vp | pr | q+a_t | a_b] ----------------
__global__ void k_build_inp() {
    int r = blockIdx.x;   // 0..1023 = (b*8+s)*16+a
    int b = r >> 7;
    size_t base = (size_t)r * 3072;
    for (int d = threadIdx.x; d < 768; d += blockDim.x) {
        g_inp[base + d] = g_vp[b * 768 + d];
        g_inp[base + 768 + d] = g_pr[b * 768 + d];
        g_inp[base + 1536 + d] = g_q[b * 768 + d] + g_at[(size_t)r * 768 + d];
        g_inp[base + 2304 + d] = g_ab[(size_t)r * 768 + d];
    }
}

// ---------------- gh[b] = whh @ h[b] + bhh, all 8 batches per block ----------------
__global__ void __launch_bounds__(128) k_gh(const float* __restrict__ whh,
                                            const float* __restrict__ bhh) {
    __shared__ float hs[8 * 768];
    for (int i = threadIdx.x; i < 8 * 768; i += 128) hs[i] = g_h[i];
    __syncthreads();
    int n = blockIdx.x * 128 + threadIdx.x;  // 0..2303
    float bv = bhh[n];
    float acc[8];
    #pragma unroll
    for (int b = 0; b < 8; b++) acc[b] = bv;
    const float4* wr = reinterpret_cast<const float4*>(whh + (size_t)n * 768);
    #pragma unroll 4
    for (int k4 = 0; k4 < 192; k4++) {
        float4 w = wr[k4];
        int kb = k4 * 4;
        #pragma unroll
        for (int b = 0; b < 8; b++) {
            const float* hb = hs + b * 768 + kb;
            acc[b] = fmaf(w.x, hb[0], fmaf(w.y, hb[1], fmaf(w.z, hb[2], fmaf(w.w, hb[3], acc[b]))));
        }
    }
    #pragma unroll
    for (int b = 0; b < 8; b++) g_gh[b * 2304 + n] = acc[b];
}

// ---------------- GRU elementwise for step s ----------------
__global__ void k_gru(int s) {
    int blk = blockIdx.x;  // b*16+a
    int b = blk >> 4;
    int a = blk & 15;
    size_t gi_base = (size_t)((b * 8 + s) * 16 + a) * 2304;
    for (int h = threadIdx.x; h < 768; h += blockDim.x) {
        float ir = g_gi[gi_base + h];
        float iz = g_gi[gi_base + 768 + h];
        float in_ = g_gi[gi_base + 1536 + h];
        float hr = g_gh[b * 2304 + h];
        float hz = g_gh[b * 2304 + 768 + h];
        float hn = g_gh[b * 2304 + 1536 + h];
        float rr = 1.f / (1.f + expf(-(ir + hr)));
        float zz = 1.f / (1.f + expf(-(iz + hz)));
        float nn = tanhf(in_ + rr * hn);
        float hprev = g_h[b * 768 + h];
        g_states[(size_t)blk * 768 + h] = (1.f - zz) * nn + zz * hprev;
    }
}

// ---------------- logits, argmax (first-max), h <- x[best] ----------------
__global__ void __launch_bounds__(256) k_out(const float* __restrict__ w2,
                                             const float* __restrict__ b2,
                                             float* __restrict__ out, int s) {
    __shared__ float slog[16];
    __shared__ int sbest;
    int b = blockIdx.x;
    int warp = threadIdx.x >> 5, lane = threadIdx.x & 31;
    for (int a = warp; a < 16; a += 8) {
        const float* hrow = g_hid + (size_t)(b * 16 + a) * 768;
        float dot = 0.f;
        for (int dd = lane; dd < 768; dd += 32) dot = fmaf(hrow[dd], w2[dd], dot);
        #pragma unroll
        for (int o = 16; o > 0; o >>= 1) dot += __shfl_xor_sync(0xffffffffu, dot, o);
        if (lane == 0) {
            float lg = dot + b2[0];
            slog[a] = lg;
            out[(b * 8 + s) * 16 + a] = lg;
        }
    }
    __syncthreads();
    if (threadIdx.x == 0) {
        int best = 0;
        float bv = slog[0];
        #pragma unroll
        for (int a = 1; a < 16; a++)
            if (slog[a] > bv) { bv = slog[a]; best = a; }
        sbest = best;
    }
    __syncthreads();
    const float* xr = g_x + (size_t)((b * 8 + s) * 16 + sbest) * 768;
    for (int d2 = threadIdx.x; d2 < 768; d2 += 256) g_h[b * 768 + d2] = xr[d2];
}

// ---------------- host ----------------
extern "C" void kernel_launch(void* const* d_in, const int* in_sizes, int n_in,
                              void* d_out, int out_size) {
    (void)in_sizes; (void)n_in; (void)out_size;
    const float* video     = (const float*)d_in[0];
    const float* para      = (const float*)d_in[1];
    const float* question  = (const float*)d_in[2];
    const float* pscore    = (const float*)d_in[3];
    const float* a_texts   = (const float*)d_in[4];
    const float* a_buttons = (const float*)d_in[5];
    const float* mv_w1 = (const float*)d_in[6],  *mv_b1 = (const float*)d_in[7];
    const float* mv_w2 = (const float*)d_in[8],  *mv_b2 = (const float*)d_in[9];
    const float* mt_w1 = (const float*)d_in[10], *mt_b1 = (const float*)d_in[11];
    const float* mt_w2 = (const float*)d_in[12], *mt_b2 = (const float*)d_in[13];
    const float* mp_w1 = (const float*)d_in[14], *mp_b1 = (const float*)d_in[15];
    const float* mp_w2 = (const float*)d_in[16], *mp_b2 = (const float*)d_in[17];
    const float* wih   = (const float*)d_in[18], *bih   = (const float*)d_in[19];
    const float* whh   = (const float*)d_in[20], *bhh   = (const float*)d_in[21];
    const float* pr_w1 = (const float*)d_in[22], *pr_b1 = (const float*)d_in[23];
    const float* pr_w2 = (const float*)d_in[24], *pr_b2 = (const float*)d_in[25];
    const float* state0 = (const float*)d_in[26];
    float* out = (float*)d_out;

    float *pR1, *pseg, *pvpre, *pvp, *pparah, *pparao, *ppr, *pqh, *pq;
    float *pth, *pat, *pab, *pinp, *ppreh, *px, *pgi, *pstates, *phid;
    cudaGetSymbolAddress((void**)&pR1, g_R1);
    cudaGetSymbolAddress((void**)&pseg, g_segmean);
    cudaGetSymbolAddress((void**)&pvpre, g_vp_pre);
    cudaGetSymbolAddress((void**)&pvp, g_vp);
    cudaGetSymbolAddress((void**)&pparah, g_para_h);
    cudaGetSymbolAddress((void**)&pparao, g_para_o);
    cudaGetSymbolAddress((void**)&ppr, g_pr);
    cudaGetSymbolAddress((void**)&pqh, g_qh);
    cudaGetSymbolAddress((void**)&pq, g_q);
    cudaGetSymbolAddress((void**)&pth, g_th);
    cudaGetSymbolAddress((void**)&pat, g_at);
    cudaGetSymbolAddress((void**)&pab, g_ab);
    cudaGetSymbolAddress((void**)&pinp, g_inp);
    cudaGetSymbolAddress((void**)&ppreh, g_preh);
    cudaGetSymbolAddress((void**)&px, g_x);
    cudaGetSymbolAddress((void**)&pgi, g_gi);
    cudaGetSymbolAddress((void**)&pstates, g_states);
    cudaGetSymbolAddress((void**)&phid, g_hid);

    // softmax(paras_score) + h := state0
    k_softmax_init<<<1, 256>>>(pscore, state0);

    // video path: relu layer1 -> segment means -> ps-weighted sum -> layer2
    k_gemm128<true, false><<<dim3(6, 128), 256>>>(video, mv_w1, mv_b1, pR1, 16384, 768, 768);
    k_segmean<<<dim3(3, 128), 256>>>();
    k_wsum<<<dim3(3, 8), 256>>>(pseg, pvpre);
    k_gemm16<false><<<dim3(6, 1), 256>>>(pvpre, mv_w2, mv_b2, pvp, 8, 768, 768);

    // para path
    k_gemm16<true><<<dim3(6, 8), 256>>>(para, mt_w1, mt_b1, pparah, 128, 768, 768);
    k_gemm16<false><<<dim3(6, 8), 256>>>(pparah, mt_w2, mt_b2, pparao, 128, 768, 768);
    k_wsum<<<dim3(3, 8), 256>>>(pparao, ppr);

    // question path
    k_gemm16<true><<<dim3(6, 1), 256>>>(question, mt_w1, mt_b1, pqh, 8, 768, 768);
    k_gemm16<false><<<dim3(6, 1), 256>>>(pqh, mt_w2, mt_b2, pq, 8, 768, 768);

    // a_texts via mlp_t, a_buttons via mlp_v (1024 rows each)
    k_gemm128<true, false><<<dim3(6, 8), 256>>>(a_texts, mt_w1, mt_b1, pth, 1024, 768, 768);
    k_gemm128<false, false><<<dim3(6, 8), 256>>>(pth, mt_w2, mt_b2, pat, 1024, 768, 768);
    k_gemm128<true, false><<<dim3(6, 8), 256>>>(a_buttons, mv_w1, mv_b1, pth, 1024, 768, 768);
    k_gemm128<false, false><<<dim3(6, 8), 256>>>(pth, mv_w2, mv_b2, pab, 1024, 768, 768);

    // mlp_pre over all (b,s,a), then gi = x @ wih^T + bih (also h-independent)
    k_build_inp<<<1024, 256>>>();
    k_gemm128<true, false><<<dim3(24, 8), 256>>>(pinp, mp_w1, mp_b1, ppreh, 1024, 3072, 3072);
    k_gemm128<false, false><<<dim3(6, 8), 256>>>(ppreh, mp_w2, mp_b2, px, 1024, 768, 3072);
    k_gemm128<false, true><<<dim3(18, 8), 256>>>(px, wih, bih, pgi, 1024, 2304, 768);

    // sequential scan: only gh / GRU / proj / argmax-select depend on h
    for (int s = 0; s < 8; s++) {
        k_gh<<<18, 128>>>(whh, bhh);
        k_gru<<<128, 256>>>(s);
        k_gemm16<true><<<dim3(6, 8), 256>>>(pstates, pr_w1, pr_b1, phid, 128, 768, 768);
        k_out<<<8, 256>>>(pr_w2, pr_b2, out, s);
    }
}

// round 3
// speedup vs baseline: 2.1141x; 2.1141x over previous
#include <cuda_runtime.h>
#include <cuda_fp16.h>
#include <math.h>
#include <stdint.h>

// B=8, T=2048, P=16, S=8, A=16, D=768, H=768, 3H=2304, 4D=3072

// ==================== scratch (device globals) ====================
__device__ float g_ps[8 * 16];
__device__ float g_h[8 * 768];
__device__ __align__(128) float g_R1[16384 * 768];
__device__ float g_segmean[128 * 768];
__device__ float g_vp_pre[8 * 768];
__device__ float g_vp[8 * 768];
__device__ float g_para_h[128 * 768];
__device__ float g_para_o[128 * 768];
__device__ float g_pr[8 * 768];
__device__ float g_qh[8 * 768];
__device__ float g_q[8 * 768];
__device__ __align__(128) float g_at[1024 * 768];
__device__ __align__(128) float g_ab[1024 * 768];
__device__ __align__(128) float g_x[1024 * 768];
__device__ __align__(128) float g_gi[1024 * 2304];
__device__ float g_gh[8 * 2304];
__device__ float g_states[128 * 768];
__device__ float g_hid[128 * 768];

// fp16 buffers (hi/lo split)
__device__ __align__(128) __half g_vid_hi[16384 * 768];
__device__ __align__(128) __half g_atx_hi[1024 * 768];
__device__ __align__(128) __half g_atx_lo[1024 * 768];
__device__ __align__(128) __half g_abt_hi[1024 * 768];
__device__ __align__(128) __half g_abt_lo[1024 * 768];
__device__ __align__(128) __half g_wih_hi[2304 * 768];
__device__ __align__(128) __half g_wih_lo[2304 * 768];
__device__ __align__(128) __half g_mvw1t_hi[768 * 768];
__device__ __align__(128) __half g_mvw1t_lo[768 * 768];
__device__ __align__(128) __half g_mvw2t_hi[768 * 768];
__device__ __align__(128) __half g_mvw2t_lo[768 * 768];
__device__ __align__(128) __half g_mtw1t_hi[768 * 768];
__device__ __align__(128) __half g_mtw1t_lo[768 * 768];
__device__ __align__(128) __half g_mtw2t_hi[768 * 768];
__device__ __align__(128) __half g_mtw2t_lo[768 * 768];
__device__ __align__(128) __half g_mpw1t_hi[3072 * 3072];
__device__ __align__(128) __half g_mpw1t_lo[3072 * 3072];
__device__ __align__(128) __half g_mpw2t_hi[768 * 3072];
__device__ __align__(128) __half g_mpw2t_lo[768 * 3072];
__device__ __align__(128) __half g_th_hi[1024 * 768];
__device__ __align__(128) __half g_th_lo[1024 * 768];
__device__ __align__(128) __half g_inp_hi[1024 * 3072];
__device__ __align__(128) __half g_inp_lo[1024 * 3072];
__device__ __align__(128) __half g_preh_hi[1024 * 3072];
__device__ __align__(128) __half g_preh_lo[1024 * 3072];
__device__ __align__(128) __half g_x_hi[1024 * 768];
__device__ __align__(128) __half g_x_lo[1024 * 768];

// ==================== mma.sync helpers (baseline sm_80 PTX) ====================
__device__ __forceinline__ void ldm_x4(uint32_t f[4], uint32_t addr) {
    asm volatile("ldmatrix.sync.aligned.m8n8.x4.shared.b16 {%0,%1,%2,%3}, [%4];"
                 : "=r"(f[0]), "=r"(f[1]), "=r"(f[2]), "=r"(f[3]) : "r"(addr));
}
__device__ __forceinline__ void mma16816(float* c, const uint32_t a[4],
                                         uint32_t b0, uint32_t b1) {
    asm volatile(
        "mma.sync.aligned.m16n8k16.row.col.f32.f16.f16.f32 "
        "{%0,%1,%2,%3}, {%4,%5,%6,%7}, {%8,%9}, {%0,%1,%2,%3};"
        : "+f"(c[0]), "+f"(c[1]), "+f"(c[2]), "+f"(c[3])
        : "r"(a[0]), "r"(a[1]), "r"(a[2]), "r"(a[3]), "r"(b0), "r"(b1));
}
#define CP_ASYNC16(dst, src) \
    asm volatile("cp.async.cg.shared.global [%0], [%1], 16;" :: "r"(dst), "l"(src))
#define CP_COMMIT() asm volatile("cp.async.commit_group;")
#define CP_WAIT(n)  asm volatile("cp.async.wait_group %0;" :: "n"(n))

// ==================== HMMA GEMM ====================
// C[M,N] = act( A @ B^T + bias ), A:[M,K] row-major fp16 (hi/lo), B:[N,K] row-major
// fp16 (hi/lo, i.e. pre-transposed weights). fp32 accumulation via mma.sync.
// NPROD==3: hi*hi + hi*lo + lo*hi (K-advance 32/chunk).  NPROD==1: hi only (64/chunk).
// SMEM tiles: rows of 128 bytes (64 fp16), 16B-chunk XOR swizzle ch^=(row&7)
// -> conflict-free ldmatrix. CTA tile MT x 128, 8 warps (2 x 4), warp tile (MT/2) x 32.
template <int MT, int NPROD, bool RELU, bool SPLITOUT, bool F32OUT>
__global__ void __launch_bounds__(256, 1) k_hmma(
    const __half* __restrict__ Ahi, const __half* __restrict__ Alo,
    const __half* __restrict__ Bhi, const __half* __restrict__ Blo,
    const float* __restrict__ bias,
    float* __restrict__ C, __half* __restrict__ Chi, __half* __restrict__ Clo,
    int M, int N, int K)
{
    extern __shared__ __align__(128) char smem[];
    const uint32_t s_base = (uint32_t)__cvta_generic_to_shared(smem);
    constexpr int STAGE_BYTES = (MT + 128) * 128;   // A tile + B tile
    constexpr int MI = MT / 32;                      // m16-tiles per warp
    constexpr int KADV = (NPROD == 3) ? 32 : 64;
    constexpr int ACP = MT * 8;                      // A 16B-chunks per stage

    const int tid = threadIdx.x;
    const int wid = tid >> 5, lane = tid & 31;
    const int wm = wid & 1, wn = wid >> 1;
    const int row0 = blockIdx.y * MT;
    const int col0 = blockIdx.x * 128;
    const int NC = K / KADV;

    float acc[MI][4][4];
    #pragma unroll
    for (int i = 0; i < MI; i++)
        #pragma unroll
        for (int j = 0; j < 4; j++)
            #pragma unroll
            for (int r = 0; r < 4; r++) acc[i][j][r] = 0.f;

    auto load_stage = [&](int c) {
        const int k0 = c * KADV;
        const uint32_t sb = s_base + (uint32_t)((c & 1) * STAGE_BYTES);
        #pragma unroll
        for (int i = tid; i < ACP + 1024; i += 256) {
            const bool isA = i < ACP;
            const int e = isA ? i : i - ACP;
            const int row = e >> 3, ch = e & 7;
            const int grow = (isA ? row0 : col0) + row;
            const __half* src;
            if (NPROD == 3) {
                const int op = ch >> 2, kc = ch & 3;
                const __half* base = isA ? (op ? Alo : Ahi) : (op ? Blo : Bhi);
                src = base + (size_t)grow * K + k0 + kc * 8;
            } else {
                src = (isA ? Ahi : Bhi) + (size_t)grow * K + k0 + ch * 8;
            }
            const uint32_t dst = sb + (uint32_t)((isA ? 0 : MT * 128)
                               + row * 128 + ((ch ^ (row & 7)) << 4));
            CP_ASYNC16(dst, src);
        }
        CP_COMMIT();
    };

    load_stage(0);

    for (int c = 0; c < NC; c++) {
        if (c + 1 < NC) { load_stage(c + 1); CP_WAIT(1); }
        else            { CP_WAIT(0); }
        __syncthreads();

        const uint32_t sA = s_base + (uint32_t)((c & 1) * STAGE_BYTES);
        const uint32_t sB = sA + MT * 128;

        #pragma unroll
        for (int p = 0; p < NPROD; p++) {
            const int aop = (p == 2) ? 1 : 0;
            const int bop = (p == 1) ? 1 : 0;
            constexpr int NK = (NPROD == 3) ? 2 : 4;
            #pragma unroll
            for (int s = 0; s < NK; s++) {
                uint32_t af[MI][4];
                #pragma unroll
                for (int mt = 0; mt < MI; mt++) {
                    const int row = wm * (MT / 2) + mt * 16 + (lane & 15);
                    const int ch = aop * 4 + s * 2 + (lane >> 4);
                    ldm_x4(af[mt], sA + row * 128 + ((ch ^ (row & 7)) << 4));
                }
                uint32_t bf[2][4];
                #pragma unroll
                for (int ntp = 0; ntp < 2; ntp++) {
                    const int row = wn * 32 + ntp * 16 + ((lane >> 4) << 3) + (lane & 7);
                    const int ch = bop * 4 + s * 2 + ((lane >> 3) & 1);
                    ldm_x4(bf[ntp], sB + row * 128 + ((ch ^ (row & 7)) << 4));
                }
                #pragma unroll
                for (int mt = 0; mt < MI; mt++)
                    #pragma unroll
                    for (int nt = 0; nt < 4; nt++)
                        mma16816(acc[mt][nt], af[mt],
                                 bf[nt >> 1][(nt & 1) * 2],
                                 bf[nt >> 1][(nt & 1) * 2 + 1]);
            }
        }
        __syncthreads();
    }

    // epilogue: d0,d1 -> (row l/4, col 2(l%4)); d2,d3 -> row+8
    #pragma unroll
    for (int mt = 0; mt < MI; mt++) {
        #pragma unroll
        for (int nt = 0; nt < 4; nt++) {
            const int col = col0 + wn * 32 + nt * 8 + (lane & 3) * 2;
            const float2 bv = *reinterpret_cast<const float2*>(bias + col);
            #pragma unroll
            for (int half = 0; half < 2; half++) {
                const int grow = row0 + wm * (MT / 2) + mt * 16 + (lane >> 2) + half * 8;
                float v0 = acc[mt][nt][half * 2 + 0] + bv.x;
                float v1 = acc[mt][nt][half * 2 + 1] + bv.y;
                if (RELU) { v0 = fmaxf(v0, 0.f); v1 = fmaxf(v1, 0.f); }
                if (F32OUT)
                    *reinterpret_cast<float2*>(C + (size_t)grow * N + col) =
                        make_float2(v0, v1);
                if (SPLITOUT) {
                    const __half h0 = __float2half_rn(v0);
                    const __half h1 = __float2half_rn(v1);
                    const __half l0 = __float2half_rn(v0 - __half2float(h0));
                    const __half l1 = __float2half_rn(v1 - __half2float(h1));
                    *reinterpret_cast<__half2*>(Chi + (size_t)grow * N + col) =
                        make_half2(h0, h1);
                    *reinterpret_cast<__half2*>(Clo + (size_t)grow * N + col) =
                        make_half2(l0, l1);
                }
            }
        }
    }
}

// ==================== conversion kernels ====================
__global__ void k_half(const float* __restrict__ in, __half* __restrict__ hi, int n4) {
    int i = blockIdx.x * 256 + threadIdx.x;
    if (i >= n4) return;
    float4 v = reinterpret_cast<const float4*>(in)[i];
    reinterpret_cast<__half2*>(hi)[i * 2 + 0] =
        make_half2(__float2half_rn(v.x), __float2half_rn(v.y));
    reinterpret_cast<__half2*>(hi)[i * 2 + 1] =
        make_half2(__float2half_rn(v.z), __float2half_rn(v.w));
}

__global__ void k_split(const float* __restrict__ in, __half* __restrict__ hi,
                        __half* __restrict__ lo, int n4) {
    int i = blockIdx.x * 256 + threadIdx.x;
    if (i >= n4) return;
    float4 v = reinterpret_cast<const float4*>(in)[i];
    __half h0 = __float2half_rn(v.x), h1 = __float2half_rn(v.y);
    __half h2 = __float2half_rn(v.z), h3 = __float2half_rn(v.w);
    __half l0 = __float2half_rn(v.x - __half2float(h0));
    __half l1 = __float2half_rn(v.y - __half2float(h1));
    __half l2 = __float2half_rn(v.z - __half2float(h2));
    __half l3 = __float2half_rn(v.w - __half2float(h3));
    reinterpret_cast<__half2*>(hi)[i * 2 + 0] = make_half2(h0, h1);
    reinterpret_cast<__half2*>(hi)[i * 2 + 1] = make_half2(h2, h3);
    reinterpret_cast<__half2*>(lo)[i * 2 + 0] = make_half2(l0, l1);
    reinterpret_cast<__half2*>(lo)[i * 2 + 1] = make_half2(l2, l3);
}

// W [K, N] fp32 -> out [N, K] fp16 hi/lo (transpose + split)
__global__ void k_splitT(const float* __restrict__ W, __half* __restrict__ hi,
                         __half* __restrict__ lo, int K, int N) {
    __shared__ float t[32][33];
    const int kb = blockIdx.y * 32, nb = blockIdx.x * 32;
    const int tx = threadIdx.x & 31, ty = threadIdx.x >> 5;
    #pragma unroll
    for (int r = ty; r < 32; r += 8)
        t[r][tx] = W[(size_t)(kb + r) * N + nb + tx];
    __syncthreads();
    #pragma unroll
    for (int r = ty; r < 32; r += 8) {
        float v = t[tx][r];
        __half h = __float2half_rn(v);
        __half l = __float2half_rn(v - __half2float(h));
        size_t o = (size_t)(nb + r) * K + kb + tx;
        hi[o] = h;
        lo[o] = l;
    }
}

// ==================== fp32 helper kernels (validated in R1) ====================
__global__ void k_softmax_init(const float* __restrict__ scores,
                               const float* __restrict__ state0) {
    int tid = threadIdx.x;
    int warp = tid >> 5, lane = tid & 31;
    if (warp < 8) {
        float v = (lane < 16) ? scores[warp * 16 + lane] : -1e30f;
        float m = v;
        #pragma unroll
        for (int o = 16; o > 0; o >>= 1) m = fmaxf(m, __shfl_xor_sync(0xffffffffu, m, o));
        float e = (lane < 16) ? expf(v - m) : 0.f;
        float s = e;
        #pragma unroll
        for (int o = 16; o > 0; o >>= 1) s += __shfl_xor_sync(0xffffffffu, s, o);
        if (lane < 16) g_ps[warp * 16 + lane] = e / s;
    }
    for (int i = tid; i < 8 * 768; i += blockDim.x) g_h[i] = state0[i % 768];
}

template <bool RELU>
__global__ void __launch_bounds__(256) k_gemm16(
    const float* __restrict__ A, const float* __restrict__ W,
    const float* __restrict__ bias, float* __restrict__ C,
    int M, int N, int K) {
    __shared__ __align__(16) float As[32][16];
    __shared__ __align__(16) float Ws[32][128];
    const int tid = threadIdx.x;
    const int row0 = blockIdx.y * 16;
    const int col0 = blockIdx.x * 128;
    const int row = tid >> 4;
    const int cg = tid & 15;
    float acc[8];
    #pragma unroll
    for (int j = 0; j < 8; j++) acc[j] = 0.f;
    for (int k0 = 0; k0 < K; k0 += 32) {
        if (tid < 128) {
            int ar = tid >> 3, ac = (tid & 7) * 4;
            float4 av = make_float4(0.f, 0.f, 0.f, 0.f);
            int gr = row0 + ar;
            if (gr < M) av = *reinterpret_cast<const float4*>(A + (size_t)gr * K + k0 + ac);
            As[ac + 0][ar] = av.x; As[ac + 1][ar] = av.y;
            As[ac + 2][ar] = av.z; As[ac + 3][ar] = av.w;
        }
        #pragma unroll
        for (int j = 0; j < 4; j++) {
            int wr = (tid >> 5) + j * 8;
            int wc = (tid & 31) * 4;
            float4 wv = *reinterpret_cast<const float4*>(W + (size_t)(k0 + wr) * N + col0 + wc);
            *reinterpret_cast<float4*>(&Ws[wr][wc]) = wv;
        }
        __syncthreads();
        #pragma unroll
        for (int k = 0; k < 32; k++) {
            float a = As[k][row];
            float4 b0 = *reinterpret_cast<const float4*>(&Ws[k][cg * 4]);
            float4 b1 = *reinterpret_cast<const float4*>(&Ws[k][64 + cg * 4]);
            acc[0] = fmaf(a, b0.x, acc[0]); acc[1] = fmaf(a, b0.y, acc[1]);
            acc[2] = fmaf(a, b0.z, acc[2]); acc[3] = fmaf(a, b0.w, acc[3]);
            acc[4] = fmaf(a, b1.x, acc[4]); acc[5] = fmaf(a, b1.y, acc[5]);
            acc[6] = fmaf(a, b1.z, acc[6]); acc[7] = fmaf(a, b1.w, acc[7]);
        }
        __syncthreads();
    }
    int r = row0 + row;
    if (r < M) {
        float4 bv0 = *reinterpret_cast<const float4*>(bias + col0 + cg * 4);
        float4 bv1 = *reinterpret_cast<const float4*>(bias + col0 + 64 + cg * 4);
        float o[8];
        o[0] = acc[0] + bv0.x; o[1] = acc[1] + bv0.y;
        o[2] = acc[2] + bv0.z; o[3] = acc[3] + bv0.w;
        o[4] = acc[4] + bv1.x; o[5] = acc[5] + bv1.y;
        o[6] = acc[6] + bv1.z; o[7] = acc[7] + bv1.w;
        if (RELU) {
            #pragma unroll
            for (int j = 0; j < 8; j++) o[j] = fmaxf(o[j], 0.f);
        }
        *reinterpret_cast<float4*>(C + (size_t)r * N + col0 + cg * 4) =
            make_float4(o[0], o[1], o[2], o[3]);
        *reinterpret_cast<float4*>(C + (size_t)r * N + col0 + 64 + cg * 4) =
            make_float4(o[4], o[5], o[6], o[7]);
    }
}

__global__ void k_segmean() {
    int bp = blockIdx.y;
    int d = blockIdx.x * 256 + threadIdx.x;
    const float* src = g_R1 + (size_t)bp * 128 * 768 + d;
    float acc = 0.f;
    #pragma unroll 8
    for (int j = 0; j < 128; j++) acc += src[(size_t)j * 768];
    g_segmean[bp * 768 + d] = acc * (1.f / 128.f);
}

__global__ void k_wsum(const float* __restrict__ in, float* __restrict__ out) {
    int b = blockIdx.y;
    int d = blockIdx.x * 256 + threadIdx.x;
    float acc = 0.f;
    #pragma unroll
    for (int p = 0; p < 16; p++)
        acc = fmaf(g_ps[b * 16 + p], in[(size_t)(b * 16 + p) * 768 + d], acc);
    out[b * 768 + d] = acc;
}

// build mlp_pre input as fp16 hi/lo: [vp | pr | q+a_t | a_b]
__global__ void k_build_inp() {
    int r = blockIdx.x;
    int b = r >> 7;
    size_t base = (size_t)r * 3072;
    for (int d = threadIdx.x; d < 768; d += blockDim.x) {
        float v[4];
        v[0] = g_vp[b * 768 + d];
        v[1] = g_pr[b * 768 + d];
        v[2] = g_q[b * 768 + d] + g_at[(size_t)r * 768 + d];
        v[3] = g_ab[(size_t)r * 768 + d];
        #pragma unroll
        for (int s = 0; s < 4; s++) {
            __half h = __float2half_rn(v[s]);
            __half l = __float2half_rn(v[s] - __half2float(h));
            g_inp_hi[base + s * 768 + d] = h;
            g_inp_lo[base + s * 768 + d] = l;
        }
    }
}

__global__ void __launch_bounds__(128) k_gh(const float* __restrict__ whh,
                                            const float* __restrict__ bhh) {
    __shared__ float hs[8 * 768];
    for (int i = threadIdx.x; i < 8 * 768; i += 128) hs[i] = g_h[i];
    __syncthreads();
    int n = blockIdx.x * 128 + threadIdx.x;
    float bv = bhh[n];
    float acc[8];
    #pragma unroll
    for (int b = 0; b < 8; b++) acc[b] = bv;
    const float4* wr = reinterpret_cast<const float4*>(whh + (size_t)n * 768);
    #pragma unroll 4
    for (int k4 = 0; k4 < 192; k4++) {
        float4 w = wr[k4];
        int kb = k4 * 4;
        #pragma unroll
        for (int b = 0; b < 8; b++) {
            const float* hb = hs + b * 768 + kb;
            acc[b] = fmaf(w.x, hb[0], fmaf(w.y, hb[1], fmaf(w.z, hb[2], fmaf(w.w, hb[3], acc[b]))));
        }
    }
    #pragma unroll
    for (int b = 0; b < 8; b++) g_gh[b * 2304 + n] = acc[b];
}

__global__ void k_gru(int s) {
    int blk = blockIdx.x;
    int b = blk >> 4;
    int a = blk & 15;
    size_t gi_base = (size_t)((b * 8 + s) * 16 + a) * 2304;
    for (int h = threadIdx.x; h < 768; h += blockDim.x) {
        float ir = g_gi[gi_base + h];
        float iz = g_gi[gi_base + 768 + h];
        float in_ = g_gi[gi_base + 1536 + h];
        float hr = g_gh[b * 2304 + h];
        float hz = g_gh[b * 2304 + 768 + h];
        float hn = g_gh[b * 2304 + 1536 + h];
        float rr = 1.f / (1.f + expf(-(ir + hr)));
        float zz = 1.f / (1.f + expf(-(iz + hz)));
        float nn = tanhf(in_ + rr * hn);
        float hprev = g_h[b * 768 + h];
        g_states[(size_t)blk * 768 + h] = (1.f - zz) * nn + zz * hprev;
    }
}

__global__ void __launch_bounds__(256) k_out(const float* __restrict__ w2,
                                             const float* __restrict__ b2,
                                             float* __restrict__ out, int s) {
    __shared__ float slog[16];
    __shared__ int sbest;
    int b = blockIdx.x;
    int warp = threadIdx.x >> 5, lane = threadIdx.x & 31;
    for (int a = warp; a < 16; a += 8) {
        const float* hrow = g_hid + (size_t)(b * 16 + a) * 768;
        float dot = 0.f;
        for (int dd = lane; dd < 768; dd += 32) dot = fmaf(hrow[dd], w2[dd], dot);
        #pragma unroll
        for (int o = 16; o > 0; o >>= 1) dot += __shfl_xor_sync(0xffffffffu, dot, o);
        if (lane == 0) {
            float lg = dot + b2[0];
            slog[a] = lg;
            out[(b * 8 + s) * 16 + a] = lg;
        }
    }
    __syncthreads();
    if (threadIdx.x == 0) {
        int best = 0;
        float bv = slog[0];
        #pragma unroll
        for (int a = 1; a < 16; a++)
            if (slog[a] > bv) { bv = slog[a]; best = a; }
        sbest = best;
    }
    __syncthreads();
    const float* xr = g_x + (size_t)((b * 8 + s) * 16 + sbest) * 768;
    for (int d2 = threadIdx.x; d2 < 768; d2 += 256) g_h[b * 768 + d2] = xr[d2];
}

// ==================== host ====================
#define GETSYM(p, s) cudaGetSymbolAddress((void**)&(p), s)

extern "C" void kernel_launch(void* const* d_in, const int* in_sizes, int n_in,
                              void* d_out, int out_size) {
    (void)in_sizes; (void)n_in; (void)out_size;
    const float* video     = (const float*)d_in[0];
    const float* para      = (const float*)d_in[1];
    const float* question  = (const float*)d_in[2];
    const float* pscore    = (const float*)d_in[3];
    const float* a_texts   = (const float*)d_in[4];
    const float* a_buttons = (const float*)d_in[5];
    const float* mv_w1 = (const float*)d_in[6],  *mv_b1 = (const float*)d_in[7];
    const float* mv_w2 = (const float*)d_in[8],  *mv_b2 = (const float*)d_in[9];
    const float* mt_w1 = (const float*)d_in[10], *mt_b1 = (const float*)d_in[11];
    const float* mt_w2 = (const float*)d_in[12], *mt_b2 = (const float*)d_in[13];
    const float* mp_w1 = (const float*)d_in[14], *mp_b1 = (const float*)d_in[15];
    const float* mp_w2 = (const float*)d_in[16], *mp_b2 = (const float*)d_in[17];
    const float* wih   = (const float*)d_in[18], *bih   = (const float*)d_in[19];
    const float* whh   = (const float*)d_in[20], *bhh   = (const float*)d_in[21];
    const float* pr_w1 = (const float*)d_in[22], *pr_b1 = (const float*)d_in[23];
    const float* pr_w2 = (const float*)d_in[24], *pr_b2 = (const float*)d_in[25];
    const float* state0 = (const float*)d_in[26];
    float* out = (float*)d_out;

    float *pR1, *pseg, *pvpre, *pvp, *pparah, *pparao, *ppr, *pqh, *pq;
    float *pat, *pab, *px, *pgi, *pstates, *phid;
    GETSYM(pR1, g_R1); GETSYM(pseg, g_segmean); GETSYM(pvpre, g_vp_pre);
    GETSYM(pvp, g_vp); GETSYM(pparah, g_para_h); GETSYM(pparao, g_para_o);
    GETSYM(ppr, g_pr); GETSYM(pqh, g_qh); GETSYM(pq, g_q);
    GETSYM(pat, g_at); GETSYM(pab, g_ab); GETSYM(px, g_x);
    GETSYM(pgi, g_gi); GETSYM(pstates, g_states); GETSYM(phid, g_hid);

    __half *vid_hi, *atx_hi, *atx_lo, *abt_hi, *abt_lo, *wih_hi, *wih_lo;
    __half *mvw1t_hi, *mvw1t_lo, *mvw2t_hi, *mvw2t_lo, *mtw1t_hi, *mtw1t_lo;
    __half *mtw2t_hi, *mtw2t_lo, *mpw1t_hi, *mpw1t_lo, *mpw2t_hi, *mpw2t_lo;
    __half *th_hi, *th_lo, *inp_hi, *inp_lo, *preh_hi, *preh_lo, *x_hi, *x_lo;
    GETSYM(vid_hi, g_vid_hi);
    GETSYM(atx_hi, g_atx_hi); GETSYM(atx_lo, g_atx_lo);
    GETSYM(abt_hi, g_abt_hi); GETSYM(abt_lo, g_abt_lo);
    GETSYM(wih_hi, g_wih_hi); GETSYM(wih_lo, g_wih_lo);
    GETSYM(mvw1t_hi, g_mvw1t_hi); GETSYM(mvw1t_lo, g_mvw1t_lo);
    GETSYM(mvw2t_hi, g_mvw2t_hi); GETSYM(mvw2t_lo, g_mvw2t_lo);
    GETSYM(mtw1t_hi, g_mtw1t_hi); GETSYM(mtw1t_lo, g_mtw1t_lo);
    GETSYM(mtw2t_hi, g_mtw2t_hi); GETSYM(mtw2t_lo, g_mtw2t_lo);
    GETSYM(mpw1t_hi, g_mpw1t_hi); GETSYM(mpw1t_lo, g_mpw1t_lo);
    GETSYM(mpw2t_hi, g_mpw2t_hi); GETSYM(mpw2t_lo, g_mpw2t_lo);
    GETSYM(th_hi, g_th_hi); GETSYM(th_lo, g_th_lo);
    GETSYM(inp_hi, g_inp_hi); GETSYM(inp_lo, g_inp_lo);
    GETSYM(preh_hi, g_preh_hi); GETSYM(preh_lo, g_preh_lo);
    GETSYM(x_hi, g_x_hi); GETSYM(x_lo, g_x_lo);

    constexpr int SM128 = (128 + 128) * 128 * 2;  // 65536
    constexpr int SM64  = (64 + 128) * 128 * 2;   // 49152
    cudaFuncSetAttribute(k_hmma<128, 1, true,  false, true >, cudaFuncAttributeMaxDynamicSharedMemorySize, SM128);
    cudaFuncSetAttribute(k_hmma<64,  3, true,  true,  false>, cudaFuncAttributeMaxDynamicSharedMemorySize, SM64);
    cudaFuncSetAttribute(k_hmma<64,  3, false, false, true >, cudaFuncAttributeMaxDynamicSharedMemorySize, SM64);
    cudaFuncSetAttribute(k_hmma<64,  3, false, true,  true >, cudaFuncAttributeMaxDynamicSharedMemorySize, SM64);

    // softmax + h init
    k_softmax_init<<<1, 256>>>(pscore, state0);

    // conversions
    k_half<<<(16384 * 768 / 4 + 255) / 256, 256>>>(video, vid_hi, 16384 * 768 / 4);
    k_splitT<<<dim3(24, 24), 256>>>(mv_w1, mvw1t_hi, mvw1t_lo, 768, 768);
    k_splitT<<<dim3(24, 24), 256>>>(mv_w2, mvw2t_hi, mvw2t_lo, 768, 768);
    k_splitT<<<dim3(24, 24), 256>>>(mt_w1, mtw1t_hi, mtw1t_lo, 768, 768);
    k_splitT<<<dim3(24, 24), 256>>>(mt_w2, mtw2t_hi, mtw2t_lo, 768, 768);
    k_splitT<<<dim3(96, 96), 256>>>(mp_w1, mpw1t_hi, mpw1t_lo, 3072, 3072);
    k_splitT<<<dim3(24, 96), 256>>>(mp_w2, mpw2t_hi, mpw2t_lo, 3072, 768);
    k_split<<<(2304 * 768 / 4 + 255) / 256, 256>>>(wih, wih_hi, wih_lo, 2304 * 768 / 4);
    k_split<<<(1024 * 768 / 4 + 255) / 256, 256>>>(a_texts, atx_hi, atx_lo, 1024 * 768 / 4);
    k_split<<<(1024 * 768 / 4 + 255) / 256, 256>>>(a_buttons, abt_hi, abt_lo, 1024 * 768 / 4);

    // video L1 (single-fp16 HMMA; error averaged away by 128-wide segment mean)
    k_hmma<128, 1, true, false, true><<<dim3(6, 128), 256, SM128>>>(
        vid_hi, nullptr, mvw1t_hi, nullptr, mv_b1, pR1, nullptr, nullptr, 16384, 768, 768);
    k_segmean<<<dim3(3, 128), 256>>>();
    k_wsum<<<dim3(3, 8), 256>>>(pseg, pvpre);
    k_gemm16<false><<<dim3(6, 1), 256>>>(pvpre, mv_w2, mv_b2, pvp, 8, 768, 768);

    // para path (fp32, tiny)
    k_gemm16<true><<<dim3(6, 8), 256>>>(para, mt_w1, mt_b1, pparah, 128, 768, 768);
    k_gemm16<false><<<dim3(6, 8), 256>>>(pparah, mt_w2, mt_b2, pparao, 128, 768, 768);
    k_wsum<<<dim3(3, 8), 256>>>(pparao, ppr);

    // question path (fp32, tiny)
    k_gemm16<true><<<dim3(6, 1), 256>>>(question, mt_w1, mt_b1, pqh, 8, 768, 768);
    k_gemm16<false><<<dim3(6, 1), 256>>>(pqh, mt_w2, mt_b2, pq, 8, 768, 768);

    // a_texts: mlp_t (split HMMA)
    k_hmma<64, 3, true, true, false><<<dim3(6, 16), 256, SM64>>>(
        atx_hi, atx_lo, mtw1t_hi, mtw1t_lo, mt_b1, nullptr, th_hi, th_lo, 1024, 768, 768);
    k_hmma<64, 3, false, false, true><<<dim3(6, 16), 256, SM64>>>(
        th_hi, th_lo, mtw2t_hi, mtw2t_lo, mt_b2, pat, nullptr, nullptr, 1024, 768, 768);
    // a_buttons: mlp_v
    k_hmma<64, 3, true, true, false><<<dim3(6, 16), 256, SM64>>>(
        abt_hi, abt_lo, mvw1t_hi, mvw1t_lo, mv_b1, nullptr, th_hi, th_lo, 1024, 768, 768);
    k_hmma<64, 3, false, false, true><<<dim3(6, 16), 256, SM64>>>(
        th_hi, th_lo, mvw2t_hi, mvw2t_lo, mv_b2, pab, nullptr, nullptr, 1024, 768, 768);

    // mlp_pre + gi (h-independent)
    k_build_inp<<<1024, 256>>>();
    k_hmma<64, 3, true, true, false><<<dim3(24, 16), 256, SM64>>>(
        inp_hi, inp_lo, mpw1t_hi, mpw1t_lo, mp_b1, nullptr, preh_hi, preh_lo, 1024, 3072, 3072);
    k_hmma<64, 3, false, true, true><<<dim3(6, 16), 256, SM64>>>(
        preh_hi, preh_lo, mpw2t_hi, mpw2t_lo, mp_b2, px, x_hi, x_lo, 1024, 768, 3072);
    k_hmma<64, 3, false, false, true><<<dim3(18, 16), 256, SM64>>>(
        x_hi, x_lo, wih_hi, wih_lo, bih, pgi, nullptr, nullptr, 1024, 2304, 768);

    // sequential scan (fp32 exact — protects argmax)
    for (int s = 0; s < 8; s++) {
        k_gh<<<18, 128>>>(whh, bhh);
        k_gru<<<128, 256>>>(s);
        k_gemm16<true><<<dim3(6, 8), 256>>>(pstates, pr_w1, pr_b1, phid, 128, 768, 768);
        k_out<<<8, 256>>>(pr_w2, pr_b2, out, s);
    }
}